// round 11
// baseline (speedup 1.0000x reference)
#include <cuda_runtime.h>
#include <cuda_bf16.h>
#include <cstdint>

// Soft decision tree, DEPTH=8, 32 feats, 10 classes, B=131072.
// P(leaf) = (prod e over right edges) / (prod (1+e) over path), e = exp(x[f]-t).
// Fused kernel, 4 samples/thread (float4), 4-way subtree split (quarter==warp),
// combined rcp at depth-6, uint4-prepacked leaf class offsets (no unpack ALU).

#define DEPTH   8
#define N_FEAT  32
#define N_CLS   10
#define BT      128               // threads per block
#define SPB     128               // samples per block (32 lanes x 4 samples, x4 quarters)
#define PADF    132               // padded floats per feature row (132*4=528, 16B-mult)
#define N_SUB   63                // nodes per depth-2 subtree

#define LOG2E 1.4426950408889634f

__device__ __forceinline__ float ex2f(float z) {
    float e; asm("ex2.approx.f32 %0, %1;" : "=f"(e) : "f"(z)); return e;
}
__device__ __forceinline__ float rcpf(float d) {
    float r; asm("rcp.approx.f32 %0, %1;" : "=f"(r) : "f"(d)); return r;
}

__device__ __forceinline__ float4 f4_ex2_fma(float4 xv, float px) {
    float4 e;
    e.x = ex2f(fmaf(xv.x, LOG2E, px));
    e.y = ex2f(fmaf(xv.y, LOG2E, px));
    e.z = ex2f(fmaf(xv.z, LOG2E, px));
    e.w = ex2f(fmaf(xv.w, LOG2E, px));
    return e;
}
__device__ __forceinline__ float4 f4_fma(float4 a, float4 b, float4 c) {
    return make_float4(fmaf(a.x,b.x,c.x), fmaf(a.y,b.y,c.y),
                       fmaf(a.z,b.z,c.z), fmaf(a.w,b.w,c.w));
}
__device__ __forceinline__ float4 f4_mul(float4 a, float4 b) {
    return make_float4(a.x*b.x, a.y*b.y, a.z*b.z, a.w*b.w);
}
__device__ __forceinline__ float4 f4_rcp(float4 a) {
    return make_float4(rcpf(a.x), rcpf(a.y), rcpf(a.z), rcpf(a.w));
}
__device__ __forceinline__ float4 ld4(const char* p) { return *(const float4*)p; }

// ld = local depth in subtree (0..4), j = local node index.
template <int ld, int j>
struct Walk {
    static __device__ __forceinline__ void run(float4 N, float4 D,
                                               const char* xb, char* sb,
                                               const float2* ps, const uint4* pk) {
        float2 p  = ps[(1 << ld) - 1 + j];              // broadcast LDS.64
        float4 xv = ld4(xb + __float_as_int(p.y));      // LDS.128: 4 samples
        float4 e  = f4_ex2_fma(xv, p.x);
        float4 Dn = f4_fma(D, e, D);                    // D*(1+e)
        Walk<ld + 1, 2 * j>::run(N, Dn, xb, sb, ps, pk);
        Walk<ld + 1, 2 * j + 1>::run(f4_mul(N, e), Dn, xb, sb, ps, pk);
    }
};

// Depth-6 handler: node + both depth-7 children; one rcp per sample serves
// both children: r = rcp(DL*DR); 1/DL = r*DR; 1/DR = r*DL.
template <int j>
struct Walk<4, j> {
    static __device__ __forceinline__ void run(float4 N, float4 D,
                                               const char* xb, char* sb,
                                               const float2* ps, const uint4* pk) {
        float2 p6 = ps[15 + j];
        float4 e6 = f4_ex2_fma(ld4(xb + __float_as_int(p6.y)), p6.x);
        float4 D6 = f4_fma(D, e6, D);
        float4 NR = f4_mul(N, e6);

        float2 pL = ps[31 + 2 * j];
        float4 eL = f4_ex2_fma(ld4(xb + __float_as_int(pL.y)), pL.x);
        float4 DL = f4_fma(D6, eL, D6);

        float2 pR = ps[32 + 2 * j];
        float4 eR = f4_ex2_fma(ld4(xb + __float_as_int(pR.y)), pR.x);
        float4 DR = f4_fma(D6, eR, D6);

        float4 r  = f4_rcp(f4_mul(DL, DR));
        float4 iL = f4_mul(r, DR);
        float4 iR = f4_mul(r, DL);

        float4 PLL = f4_mul(N,  iL);
        float4 PLR = f4_mul(PLL, eL);
        float4 PRL = f4_mul(NR, iR);
        float4 PRR = f4_mul(PRL, eR);

        uint4 k = pk[j];                                // broadcast LDS.128
        {
            float4* a = (float4*)(sb + k.x);
            float4 v = *a; v.x += PLL.x; v.y += PLL.y; v.z += PLL.z; v.w += PLL.w; *a = v;
        }
        {
            float4* a = (float4*)(sb + k.y);
            float4 v = *a; v.x += PLR.x; v.y += PLR.y; v.z += PLR.z; v.w += PLR.w; *a = v;
        }
        {
            float4* a = (float4*)(sb + k.z);
            float4 v = *a; v.x += PRL.x; v.y += PRL.y; v.z += PRL.z; v.w += PRL.w; *a = v;
        }
        {
            float4* a = (float4*)(sb + k.w);
            float4 v = *a; v.x += PRR.x; v.y += PRR.y; v.z += PRR.z; v.w += PRR.w; *a = v;
        }
    }
};

__global__ void __launch_bounds__(BT, 5)
dt_kernel(const float* __restrict__ x,
          const float* __restrict__ thr,
          const int*   __restrict__ feats,
          const int*   __restrict__ cls,
          float* __restrict__ out) {
    __shared__ __align__(16) float    xs[N_FEAT * PADF];      // 16.9 KB, xs[f*PADF + s]
    __shared__ __align__(16) float    sacc[4 * N_CLS * SPB];  // 20 KB
    __shared__ __align__(8)  float2   s_top[3];
    __shared__ __align__(8)  float2   s_ps[4 * N_SUB];        // 2.0 KB
    __shared__ __align__(16) uint4    s_pk[64];               // 1.0 KB: [q][j] leaf offs

    const int tid  = threadIdx.x;
    const int bs   = blockIdx.x * SPB;
    const int q    = tid >> 5;             // quarter == warp index
    const int lane = tid & 31;             // owns samples 4*lane .. 4*lane+3

    // ---- per-block param prep ----
    if (tid < 3) {
        s_top[tid] = make_float2(-thr[tid] * LOG2E, __int_as_float(feats[tid] * PADF * 4));
    }
#pragma unroll
    for (int rd = 0; rd < 2; rd++) {
        int i = tid + rd * BT;
        if (i < 4 * N_SUB) {
            int qq  = i / N_SUB;
            int rem = i - qq * N_SUB;      // 0..62, level order within subtree
            int ldp = 31 - __clz(rem + 1); // 0..5
            int j   = rem + 1 - (1 << ldp);
            int g   = ((1 << (ldp + 2)) - 1) + qq * (1 << ldp) + j;
            s_ps[i] = make_float2(-thr[g] * LOG2E, __int_as_float(feats[g] * PADF * 4));
        }
    }
    if (tid < 64) {                        // d6 global index: q=tid>>4, j=tid&15
        int lb = tid * 4;                  // leaf base = q*64 + 4*j == tid*4
        s_pk[tid] = make_uint4((uint32_t)cls[lb + 0] * (SPB * 4),
                               (uint32_t)cls[lb + 1] * (SPB * 4),
                               (uint32_t)cls[lb + 2] * (SPB * 4),
                               (uint32_t)cls[lb + 3] * (SPB * 4));
    }

    // ---- stage 128 samples x 32 feats, coalesced LDG.128 ----
#pragma unroll
    for (int k = 0; k < (SPB * N_FEAT / 4) / BT; k++) {
        int idx = tid + k * BT;
        int s   = idx >> 3;
        int c4  = idx & 7;
        float4 v = reinterpret_cast<const float4*>(x + (size_t)(bs + s) * N_FEAT)[c4];
        xs[(c4 * 4 + 0) * PADF + s] = v.x;
        xs[(c4 * 4 + 1) * PADF + s] = v.y;
        xs[(c4 * 4 + 2) * PADF + s] = v.z;
        xs[(c4 * 4 + 3) * PADF + s] = v.w;
    }

    char* sb = (char*)sacc + q * (N_CLS * SPB * 4) + 16 * lane;
#pragma unroll
    for (int c = 0; c < N_CLS; c++)
        *(float4*)(sb + c * (SPB * 4)) = make_float4(0.f, 0.f, 0.f, 0.f);

    __syncthreads();

    const char* xb = (const char*)xs + 16 * lane;
    const float2* ps = s_ps + q * N_SUB;
    const uint4*  pk = s_pk + q * 16;

    // replicated top 2 levels
    float2 p0 = s_top[0];
    float4 e0 = f4_ex2_fma(ld4(xb + __float_as_int(p0.y)), p0.x);
    float4 D  = make_float4(e0.x + 1.f, e0.y + 1.f, e0.z + 1.f, e0.w + 1.f);
    float4 N  = (q & 2) ? e0 : make_float4(1.f, 1.f, 1.f, 1.f);

    float2 p1 = s_top[1 + (q >> 1)];
    float4 e1 = f4_ex2_fma(ld4(xb + __float_as_int(p1.y)), p1.x);
    D = f4_fma(D, e1, D);
    if (q & 1) N = f4_mul(N, e1);

    Walk<0, 0>::run(N, D, xb, sb, ps, pk);

    __syncthreads();

    // combine 4 quarter-accumulators, write out (thread t -> sample t)
    {
        float a[N_CLS];
#pragma unroll
        for (int c = 0; c < N_CLS; c++) {
            float v = 0.f;
#pragma unroll
            for (int qq = 0; qq < 4; qq++)
                v += sacc[qq * (N_CLS * SPB) + c * SPB + tid];
            a[c] = v;
        }
        float* o = out + (size_t)(bs + tid) * N_CLS;
#pragma unroll
        for (int c = 0; c < N_CLS; c += 2)
            *(float2*)(o + c) = make_float2(a[c], a[c + 1]);
    }
}

extern "C" void kernel_launch(void* const* d_in, const int* in_sizes, int n_in,
                              void* d_out, int out_size) {
    const float* x     = (const float*)d_in[0];
    const float* thr   = (const float*)d_in[1];
    const int*   feats = (const int*)d_in[2];
    const int*   cls   = (const int*)d_in[3];
    float*       out   = (float*)d_out;

    const int B = in_sizes[0] / N_FEAT;

    dt_kernel<<<B / SPB, BT>>>(x, thr, feats, cls, out);
}